// round 16
// baseline (speedup 1.0000x reference)
#include <cuda_runtime.h>
#include <cuda_bf16.h>

// patches: [B=2, N=49, C=8, P=256, P=256] fp32; out: [B, C, 1024, 1024] fp32.
// Inverse-gather: output (h,w) covered by tiles {h>>7-1, h>>7}x{w>>7-1, w>>7}
// clamped to [0,6]; count in {1,2,4}; out = sum / (count + 1e-8).
//
// Best-wall shape (R7): branch-free clamped 4-tile loads, 4 bc-planes per
// thread -> coverage math amortized over 16 independent float4 streaming
// loads; persistent grid-stride single wave. Division replaced by a select
// among the 3 possible reciprocals (bit-identical). Residency pinned to the
// R7-measured optimum of 3 CTAs/SM (grid = SMs*3): more resident CTAs
// deepened the L1tex queue and increased per-CTA spread without adding
// DRAM throughput.

namespace {
constexpr int NB = 2;
constexpr int NN = 49;
constexpr int NC = 8;
constexpr int PP = 256;
constexpr int HH = 1024;
constexpr int WW = 1024;
constexpr int TILES = 7;

constexpr int TOTAL_F4    = NB * NC * HH * WW / 4;  // 4,194,304
constexpr int QUARTER_F4  = TOTAL_F4 / 4;           // 1,048,576
constexpr int CH_F4       = PP * PP / 4;            // 16,384
constexpr int BATCH_F4    = NN * NC * CH_F4;
constexpr int N_STRIDE_F4 = NC * CH_F4;

constexpr int CTAS_PER_SM = 3;   // R7-measured optimum for wall time

// Precomputed reciprocals of (count + 1e-8), count in {1,2,4}.
__device__ constexpr float INV1 = 1.0f / (1.0f + 1e-8f);
__device__ constexpr float INV2 = 1.0f / (2.0f + 1e-8f);
__device__ constexpr float INV4 = 1.0f / (4.0f + 1e-8f);
}

__global__ __launch_bounds__(256) void patch_merge_gather4(
    const float* __restrict__ patches, float* __restrict__ out)
{
    const float4* __restrict__ p4 = reinterpret_cast<const float4*>(patches);
    float4* __restrict__ o4 = reinterpret_cast<float4*>(out);

    const int stride = gridDim.x * blockDim.x;

    for (int idx = blockIdx.x * blockDim.x + threadIdx.x;
         idx < QUARTER_F4; idx += stride)
    {
        int w4  = idx & (WW / 4 - 1);   // 0..255
        int t   = idx >> 8;
        int h   = t & (HH - 1);         // 0..1023
        int bc0 = t >> 10;              // 0..3
        int w   = w4 << 2;

        int thh = h >> 7, tww = w >> 7;
        int th0 = thh - 1 < 0 ? 0 : thh - 1;
        int th1 = thh > TILES - 1 ? TILES - 1 : thh;
        int tw0 = tww - 1 < 0 ? 0 : tww - 1;
        int tw1 = tww > TILES - 1 ? TILES - 1 : tww;

        float wr = (th1 != th0) ? 1.f : 0.f;   // second row slot valid
        float wc = (tw1 != tw0) ? 1.f : 0.f;   // second col slot valid

        int ph0 = h - (th0 << 7), ph1 = h - (th1 << 7);
        int pw0 = w - (tw0 << 7), pw1 = w - (tw1 << 7);

        int s00 = (th0 * TILES + tw0) * N_STRIDE_F4 + ((ph0 * PP + pw0) >> 2);
        int s01 = (th0 * TILES + tw1) * N_STRIDE_F4 + ((ph0 * PP + pw1) >> 2);
        int s10 = (th1 * TILES + tw0) * N_STRIDE_F4 + ((ph1 * PP + pw0) >> 2);
        int s11 = (th1 * TILES + tw1) * N_STRIDE_F4 + ((ph1 * PP + pw1) >> 2);

        // plane offsets for bc = bc0, bc0+4, bc0+8, bc0+12
        int base0 = bc0 * CH_F4;
        int plane[4];
        plane[0] = base0;
        plane[1] = base0 + 4 * CH_F4;
        plane[2] = base0 + BATCH_F4;
        plane[3] = base0 + BATCH_F4 + 4 * CH_F4;

        // 16 independent streaming loads, fully batched
        float4 v[16];
        #pragma unroll
        for (int k = 0; k < 4; ++k) {
            v[4 * k + 0] = __ldcs(p4 + plane[k] + s00);
            v[4 * k + 1] = __ldcs(p4 + plane[k] + s01);
            v[4 * k + 2] = __ldcs(p4 + plane[k] + s10);
            v[4 * k + 3] = __ldcs(p4 + plane[k] + s11);
        }

        float w01 = wc, w10 = wr, w11 = wr * wc;
        // count = (1+wr)*(1+wc) in {1,2,4}; select its reciprocal directly
        // (bit-identical to 1.f/(count+1e-8f)).
        float inv = (wr != 0.f) ? ((wc != 0.f) ? INV4 : INV2)
                                : ((wc != 0.f) ? INV2 : INV1);

        #pragma unroll
        for (int k = 0; k < 4; ++k) {
            float4 a;
            a.x = (v[4*k].x + w01 * v[4*k+1].x + w10 * v[4*k+2].x + w11 * v[4*k+3].x) * inv;
            a.y = (v[4*k].y + w01 * v[4*k+1].y + w10 * v[4*k+2].y + w11 * v[4*k+3].y) * inv;
            a.z = (v[4*k].z + w01 * v[4*k+1].z + w10 * v[4*k+2].z + w11 * v[4*k+3].z) * inv;
            a.w = (v[4*k].w + w01 * v[4*k+1].w + w10 * v[4*k+2].w + w11 * v[4*k+3].w) * inv;
            __stcs(o4 + idx + k * QUARTER_F4, a);
        }
    }
}

extern "C" void kernel_launch(void* const* d_in, const int* in_sizes, int n_in,
                              void* d_out, int out_size)
{
    const float* patches = (const float*)d_in[0];
    float* out = (float*)d_out;

    // Single wave at pinned residency: grid = SMs * 3 (GB300: 152*3 = 456).
    int dev = 0, sms = 152;
    cudaGetDevice(&dev);
    cudaDeviceGetAttribute(&sms, cudaDevAttrMultiProcessorCount, dev);
    int grid = sms * CTAS_PER_SM;
    int maxGrid = (QUARTER_F4 + 255) / 256;
    if (grid > maxGrid) grid = maxGrid;

    patch_merge_gather4<<<grid, 256>>>(patches, out);
}

// round 17
// speedup vs baseline: 1.0457x; 1.0457x over previous
#include <cuda_runtime.h>
#include <cuda_bf16.h>

// patches: [B=2, N=49, C=8, P=256, P=256] fp32; out: [B, C, 1024, 1024] fp32.
// Inverse-gather: output (h,w) covered by tiles {h>>7-1, h>>7}x{w>>7-1, w>>7}
// clamped to [0,6]; count in {1,2,4}; out = sum / (count + 1e-8).
//
// Final configuration (measured best of the low-issue family):
//  - branch-free clamped 4-tile loads; 4 bc-planes per thread -> coverage
//    math amortized over 16 independent float4 streaming loads (__ldcs)
//  - division replaced by select among the 3 possible reciprocals
//    (count is exactly 1, 2, or 4 -> bit-identical results)
//  - 5 CTAs/SM residency (48 regs), grid = SMs*5 single balanced wave
//    (R16 proved reduced residency costs DRAM throughput: 77% -> 70%)

namespace {
constexpr int NB = 2;
constexpr int NN = 49;
constexpr int NC = 8;
constexpr int PP = 256;
constexpr int HH = 1024;
constexpr int WW = 1024;
constexpr int TILES = 7;

constexpr int TOTAL_F4    = NB * NC * HH * WW / 4;  // 4,194,304
constexpr int QUARTER_F4  = TOTAL_F4 / 4;           // 1,048,576
constexpr int CH_F4       = PP * PP / 4;            // 16,384
constexpr int BATCH_F4    = NN * NC * CH_F4;
constexpr int N_STRIDE_F4 = NC * CH_F4;

constexpr int CTAS_PER_SM = 5;   // regs<=48 -> 5 CTAs/SM fit (64K regfile)

// Precomputed reciprocals of (count + 1e-8), count in {1,2,4}.
__device__ constexpr float INV1 = 1.0f / (1.0f + 1e-8f);
__device__ constexpr float INV2 = 1.0f / (2.0f + 1e-8f);
__device__ constexpr float INV4 = 1.0f / (4.0f + 1e-8f);
}

__global__ __launch_bounds__(256, CTAS_PER_SM) void patch_merge_gather4(
    const float* __restrict__ patches, float* __restrict__ out)
{
    const float4* __restrict__ p4 = reinterpret_cast<const float4*>(patches);
    float4* __restrict__ o4 = reinterpret_cast<float4*>(out);

    const int stride = gridDim.x * blockDim.x;

    for (int idx = blockIdx.x * blockDim.x + threadIdx.x;
         idx < QUARTER_F4; idx += stride)
    {
        int w4  = idx & (WW / 4 - 1);   // 0..255
        int t   = idx >> 8;
        int h   = t & (HH - 1);         // 0..1023
        int bc0 = t >> 10;              // 0..3
        int w   = w4 << 2;

        int thh = h >> 7, tww = w >> 7;
        int th0 = thh - 1 < 0 ? 0 : thh - 1;
        int th1 = thh > TILES - 1 ? TILES - 1 : thh;
        int tw0 = tww - 1 < 0 ? 0 : tww - 1;
        int tw1 = tww > TILES - 1 ? TILES - 1 : tww;

        float wr = (th1 != th0) ? 1.f : 0.f;   // second row slot valid
        float wc = (tw1 != tw0) ? 1.f : 0.f;   // second col slot valid

        int ph0 = h - (th0 << 7), ph1 = h - (th1 << 7);
        int pw0 = w - (tw0 << 7), pw1 = w - (tw1 << 7);

        int s00 = (th0 * TILES + tw0) * N_STRIDE_F4 + ((ph0 * PP + pw0) >> 2);
        int s01 = (th0 * TILES + tw1) * N_STRIDE_F4 + ((ph0 * PP + pw1) >> 2);
        int s10 = (th1 * TILES + tw0) * N_STRIDE_F4 + ((ph1 * PP + pw0) >> 2);
        int s11 = (th1 * TILES + tw1) * N_STRIDE_F4 + ((ph1 * PP + pw1) >> 2);

        // plane offsets for bc = bc0, bc0+4, bc0+8, bc0+12
        int base0 = bc0 * CH_F4;
        int plane[4];
        plane[0] = base0;
        plane[1] = base0 + 4 * CH_F4;
        plane[2] = base0 + BATCH_F4;
        plane[3] = base0 + BATCH_F4 + 4 * CH_F4;

        // 16 independent streaming loads, fully batched
        float4 v[16];
        #pragma unroll
        for (int k = 0; k < 4; ++k) {
            v[4 * k + 0] = __ldcs(p4 + plane[k] + s00);
            v[4 * k + 1] = __ldcs(p4 + plane[k] + s01);
            v[4 * k + 2] = __ldcs(p4 + plane[k] + s10);
            v[4 * k + 3] = __ldcs(p4 + plane[k] + s11);
        }

        float w01 = wc, w10 = wr, w11 = wr * wc;
        // count = (1+wr)*(1+wc) in {1,2,4}; select its reciprocal directly
        // (bit-identical to 1.f/(count+1e-8f)).
        float inv = (wr != 0.f) ? ((wc != 0.f) ? INV4 : INV2)
                                : ((wc != 0.f) ? INV2 : INV1);

        #pragma unroll
        for (int k = 0; k < 4; ++k) {
            float4 a;
            a.x = (v[4*k].x + w01 * v[4*k+1].x + w10 * v[4*k+2].x + w11 * v[4*k+3].x) * inv;
            a.y = (v[4*k].y + w01 * v[4*k+1].y + w10 * v[4*k+2].y + w11 * v[4*k+3].y) * inv;
            a.z = (v[4*k].z + w01 * v[4*k+1].z + w10 * v[4*k+2].z + w11 * v[4*k+3].z) * inv;
            a.w = (v[4*k].w + w01 * v[4*k+1].w + w10 * v[4*k+2].w + w11 * v[4*k+3].w) * inv;
            __stcs(o4 + idx + k * QUARTER_F4, a);
        }
    }
}

extern "C" void kernel_launch(void* const* d_in, const int* in_sizes, int n_in,
                              void* d_out, int out_size)
{
    const float* patches = (const float*)d_in[0];
    float* out = (float*)d_out;

    // Single balanced wave at 5 CTAs/SM (GB300: 152*5 = 760).
    int dev = 0, sms = 152;
    cudaGetDevice(&dev);
    cudaDeviceGetAttribute(&sms, cudaDevAttrMultiProcessorCount, dev);
    int grid = sms * CTAS_PER_SM;
    int maxGrid = (QUARTER_F4 + 255) / 256;
    if (grid > maxGrid) grid = maxGrid;

    patch_merge_gather4<<<grid, 256>>>(patches, out);
}